// round 14
// baseline (speedup 1.0000x reference)
#include <cuda_runtime.h>
#include <cuda_bf16.h>

// Shapes (fixed): B=32, D=64, N=254, L=16, H=128, P=96
#define NB 32
#define ND 64
#define NN 254
#define NL 16
#define NH 128
#define NP 96
#define PAIRS (NB*ND)          // 2048
#define XPP (NN*NL)            // 4064 floats per (b,d) pair
#define OUT_T_ELEMS (NB*NP*ND) // 196608
#define NPRE 38                // producer blocks

// ---- shared precomputed tensors (tiny) ----
__device__ __align__(16) float g_constvec[NH];
__device__ __align__(16) float g_M[NN*NL];   // M[n,l] = pos[n,:] . W_enc[l,:]
__device__ __align__(16) float g_D2[NN];     // pos[n,:] . constvec
__device__ __align__(16) float g_G[NL*NL];   // G[l',l] = W_enc[l',:] . W_enc[l,:]
__device__ __align__(16) float g_u[NL];      // W_enc[l,:] . constvec
__device__ __align__(16) float g_wb[NL];     // W_enc[l,:] . b_enc
__device__ __align__(16) float g_s0pad[4];   // [0] = b_enc . constvec
__device__ int g_flag1;                       // constvec ready (monotone across replays)
__device__ int g_done;                        // precompute producers done (monotone)

__device__ __forceinline__ int ld_acq(const int* p) {
    int v;
    asm volatile("ld.acquire.gpu.global.b32 %0, [%1];" : "=r"(v) : "l"(p));
    return v;
}

// vectorized length-128 dot with 4 accumulators
__device__ __forceinline__ float dot128(const float4* __restrict__ a,
                                        const float4* __restrict__ b) {
    float s0=0.f, s1=0.f, s2=0.f, s3=0.f;
    #pragma unroll
    for (int i = 0; i < 32; i += 4) {
        float4 a0=a[i],   b0=b[i];
        float4 a1=a[i+1], b1=b[i+1];
        float4 a2=a[i+2], b2=b[i+2];
        float4 a3=a[i+3], b3=b[i+3];
        s0 += a0.x*b0.x + a0.y*b0.y + a0.z*b0.z + a0.w*b0.w;
        s1 += a1.x*b1.x + a1.y*b1.y + a1.z*b1.z + a1.w*b1.w;
        s2 += a2.x*b2.x + a2.y*b2.y + a2.z*b2.z + a2.w*b2.w;
        s3 += a3.x*b3.x + a3.y*b3.y + a3.z*b3.z + a3.w*b3.w;
    }
    return (s0+s1)+(s2+s3);
}

__global__ __launch_bounds__(128, 6)
void k_all(const float* __restrict__ x, float* __restrict__ x_copy,
           const float* __restrict__ W_enc, const float* __restrict__ b_enc,
           const float* __restrict__ pos,
           const float* __restrict__ W1, const float* __restrict__ b1,
           const float* __restrict__ W2, const float* __restrict__ b2,
           float* __restrict__ out_t) {
    __shared__ __align__(16) float xsS[2][2][NL];   // [pair][half][l] xsum partials
    __shared__ __align__(16) float poS[2][2][NL];   // [pair][half][l] pooled partials
    __shared__ float wsumS[2][2];                   // [pair][half] |score| partials
    __shared__ __align__(16) float4 red7[2][2][24]; // [pair][half] W2 partials

    const int tid  = threadIdx.x;
    const int pid  = blockIdx.x;
    const int lane = tid & 31;
    const int wrp  = tid >> 5;
    const int q    = lane & 3;         // l-quarter index
    const int r    = lane >> 2;        // row-within-8 index
    const float4* __restrict__ pos4 = (const float4*)pos;
    const float4* __restrict__ W4   = (const float4*)W_enc;

    // ---------- inline precompute (first NPRE blocks; unchanged) ----------
    if (pid < NPRE) {
        if (pid == 0) {
            float a0=0.f, a1=0.f, a2=0.f, a3=0.f;
            #pragma unroll 2
            for (int n = 0; n < 252; n += 4) {
                a0 += __ldg(pos + (n+0)*NH + tid);
                a1 += __ldg(pos + (n+1)*NH + tid);
                a2 += __ldg(pos + (n+2)*NH + tid);
                a3 += __ldg(pos + (n+3)*NH + tid);
            }
            a0 += __ldg(pos + 252*NH + tid);
            a1 += __ldg(pos + 253*NH + tid);
            g_constvec[tid] = (float)NN * b_enc[tid] + ((a0+a1)+(a2+a3));
            __threadfence();
            __syncthreads();
            if (tid == 0) atomicAdd(&g_flag1, 1);
        } else if (pid <= 34) {
            int j = (pid-1)*128 + tid;
            if (j < NN*NL) {                         // M
                g_M[j] = dot128(pos4 + (j>>4)*32, W4 + (j&15)*32);
            } else if (j < NN*NL + NL*NL) {          // G
                int k = j - NN*NL;
                g_G[k] = dot128(W4 + (k>>4)*32, W4 + (k&15)*32);
            }
        } else {
            if (tid == 0) { while (ld_acq(&g_flag1) == 0) {} }
            __syncthreads();
            const float4* cv4 = (const float4*)g_constvec;
            int j = (pid-35)*128 + tid;
            if (j < NN) {                            // D2
                g_D2[j] = dot128(pos4 + j*32, cv4);
            } else if (j < NN + NL) {                // u
                g_u[j-NN] = dot128(W4 + (j-NN)*32, cv4);
            } else if (j < NN + 2*NL) {              // wb
                g_wb[j-NN-NL] = dot128(W4 + (j-NN-NL)*32, (const float4*)b_enc);
            } else if (j == NN + 2*NL) {             // s0
                g_s0pad[0] = dot128((const float4*)b_enc, cv4);
            }
        }
        __threadfence();
        __syncthreads();
        if (tid == 0) atomicAdd(&g_done, 1);
    }

    // ---------- main: 2 pairs per block, 2 warps per pair ----------
    const int pl   = wrp >> 1;          // pair-local index 0/1
    const int half = wrp & 1;           // row-half 0/1
    const int pair = pid*2 + pl;
    const float4* __restrict__ xp4 = (const float4*)(x + (size_t)pair * XPP);
    float4* __restrict__ xc4 = (float4*)(x_copy + (size_t)pair * XPP);
    const int ibase = half * 512;       // this warp's float4 range

    // Pass 1: stream x (cached) + passthrough copy (WRITE-BACK: stays in L2)
    // + xsum partials, 2 independent chains
    float la0=0.f, la1=0.f, la2=0.f, la3=0.f;
    float lb0=0.f, lb1=0.f, lb2=0.f, lb3=0.f;
    #pragma unroll 8
    for (int j = 0; j < 16; j += 2) {
        int i0 = ibase + j*32 + lane;
        int i1 = i0 + 32;
        if (i0 < XPP/4) {
            float4 f = xp4[i0];
            xc4[i0] = f;                   // plain store: dirty line stays in L2
            la0 += f.x; la1 += f.y; la2 += f.z; la3 += f.w;
        }
        if (i1 < XPP/4) {
            float4 f = xp4[i1];
            xc4[i1] = f;
            lb0 += f.x; lb1 += f.y; lb2 += f.z; lb3 += f.w;
        }
    }
    float ls0 = la0+lb0, ls1 = la1+lb1, ls2 = la2+lb2, ls3 = la3+lb3;
    #pragma unroll
    for (int m = 4; m <= 16; m <<= 1) {
        ls0 += __shfl_xor_sync(0xffffffffu, ls0, m);
        ls1 += __shfl_xor_sync(0xffffffffu, ls1, m);
        ls2 += __shfl_xor_sync(0xffffffffu, ls2, m);
        ls3 += __shfl_xor_sync(0xffffffffu, ls3, m);
    }
    if (lane < 4) {                      // lane a holds xsum quarter a
        float* rr = &xsS[pl][half][lane*4];
        rr[0] = ls0; rr[1] = ls1; rr[2] = ls2; rr[3] = ls3;
    }
    if (tid == 0) { while (ld_acq(&g_done) < NPRE) {} }
    __syncthreads();                                   // SYNC 1

    // combined xsum quarter for own q
    float4 xsq;
    xsq.x = xsS[pl][0][q*4+0] + xsS[pl][1][q*4+0];
    xsq.y = xsS[pl][0][q*4+1] + xsS[pl][1][q*4+1];
    xsq.z = xsS[pl][0][q*4+2] + xsS[pl][1][q*4+2];
    xsq.w = xsS[pl][0][q*4+3] + xsS[pl][1][q*4+3];

    // v (own quarter) + sS
    const float4* __restrict__ G4 = (const float4*)g_G;   // [16][4] float4
    float4 vq = __ldg(&((const float4*)g_u)[q]);
    float sS = __ldg(&g_s0pad[0]);
    #pragma unroll
    for (int lp = 0; lp < 16; lp++) {
        float xl = xsS[pl][0][lp] + xsS[pl][1][lp];
        float4 g = __ldg(&G4[lp*4 + q]);
        vq.x += xl*g.x; vq.y += xl*g.y; vq.z += xl*g.z; vq.w += xl*g.w;
        sS += xl * __ldg(g_wb + lp);
    }

    // Pass 2: fused score + pool over this warp's 128 rows (x re-read, L1-hot)
    // 2 independent pooled chains
    const float4* __restrict__ M4 = (const float4*)g_M;   // [NN][4] float4
    float pa0=0.f, pa1=0.f, pa2=0.f, pa3=0.f;
    float pb0=0.f, pb1=0.f, pb2=0.f, pb3=0.f;
    float aba=0.f, abb=0.f;
    #pragma unroll 8
    for (int j = 0; j < 16; j++) {
        int i = ibase + j*32 + lane;
        int n = half*128 + j*8 + r;
        float4 f = make_float4(0.f,0.f,0.f,0.f);
        float4 m = make_float4(0.f,0.f,0.f,0.f);
        float d2 = 0.f;
        if (n < NN) {
            f  = xp4[i];
            m  = __ldg(&M4[n*4 + q]);
            d2 = __ldg(g_D2 + n);
        }
        float part = f.x*vq.x + f.y*vq.y + f.z*vq.z + f.w*vq.w
                   + xsq.x*m.x + xsq.y*m.y + xsq.z*m.z + xsq.w*m.w;
        part += __shfl_xor_sync(0xffffffffu, part, 1);
        part += __shfl_xor_sync(0xffffffffu, part, 2);
        float a = part + sS + d2;
        if (n < NN) {
            if (j & 1) {
                pb0 += f.x*a; pb1 += f.y*a; pb2 += f.z*a; pb3 += f.w*a;
                if (q == 0) abb += fabsf(a);
            } else {
                pa0 += f.x*a; pa1 += f.y*a; pa2 += f.z*a; pa3 += f.w*a;
                if (q == 0) aba += fabsf(a);
            }
        }
    }
    float p0 = pa0+pb0, p1 = pa1+pb1, p2 = pa2+pb2, p3 = pa3+pb3;
    float myabs = aba + abb;
    #pragma unroll
    for (int m = 4; m <= 16; m <<= 1) {
        p0 += __shfl_xor_sync(0xffffffffu, p0, m);
        p1 += __shfl_xor_sync(0xffffffffu, p1, m);
        p2 += __shfl_xor_sync(0xffffffffu, p2, m);
        p3 += __shfl_xor_sync(0xffffffffu, p3, m);
        myabs += __shfl_xor_sync(0xffffffffu, myabs, m);
    }
    if (lane < 4) {
        float* rr = &poS[pl][half][lane*4];
        rr[0] = p0; rr[1] = p1; rr[2] = p2; rr[3] = p3;
    }
    if (lane == 0) wsumS[pl][half] = myabs;
    __syncthreads();                                   // SYNC 2

    const float inv = 1.0f / (wsumS[pl][0] + wsumS[pl][1]);

    // FF hidden: warp covers h = half*64 + k*32 + lane, k = 0..1
    float hdn[2];
    #pragma unroll
    for (int k = 0; k < 2; k++) {
        int h = half*64 + k*32 + lane;
        float a = 0.f;
        #pragma unroll
        for (int l = 0; l < NL; l++) {
            float plv = poS[pl][0][l] + poS[pl][1][l];
            a += plv * __ldg(W1 + l*NH + h);
        }
        a = __ldg(b1 + h) + a * inv;
        hdn[k] = a > 0.f ? a : 0.2f * a;
    }

    // W2 partials over this warp's 64 h's; 2 independent acc chains
    const float4* __restrict__ W24 = (const float4*)W2;   // [h][24] float4
    float4 acc0 = make_float4(0.f, 0.f, 0.f, 0.f);
    float4 acc1 = make_float4(0.f, 0.f, 0.f, 0.f);
    #pragma unroll
    for (int k = 0; k < 2; k++) {
        #pragma unroll 8
        for (int hh = 0; hh < 32; hh += 2) {
            float hv0 = __shfl_sync(0xffffffffu, hdn[k], hh);
            float hv1 = __shfl_sync(0xffffffffu, hdn[k], hh+1);
            if (lane < 24) {
                float4 w0 = __ldg(&W24[(half*64 + k*32 + hh  )*24 + lane]);
                float4 w1 = __ldg(&W24[(half*64 + k*32 + hh+1)*24 + lane]);
                acc0.x += hv0*w0.x; acc0.y += hv0*w0.y; acc0.z += hv0*w0.z; acc0.w += hv0*w0.w;
                acc1.x += hv1*w1.x; acc1.y += hv1*w1.y; acc1.z += hv1*w1.z; acc1.w += hv1*w1.w;
            }
        }
    }
    if (lane < 24) {
        float4 acc = make_float4(acc0.x+acc1.x, acc0.y+acc1.y, acc0.z+acc1.z, acc0.w+acc1.w);
        red7[pl][half][lane] = acc;
    }
    __syncthreads();                                   // SYNC 3

    if (half == 0 && lane < 24) {
        float4 t0 = red7[pl][0][lane];
        float4 t1 = red7[pl][1][lane];
        float4 bb = __ldg(&((const float4*)b2)[lane]);
        int b = pair >> 6, d = pair & 63;
        float* dst = out_t + b*(NP*ND) + d;
        int p = lane*4;
        dst[(p+0)*ND] = t0.x + t1.x + bb.x;
        dst[(p+1)*ND] = t0.y + t1.y + bb.y;
        dst[(p+2)*ND] = t0.z + t1.z + bb.z;
        dst[(p+3)*ND] = t0.w + t1.w + bb.w;
    }
}

extern "C" void kernel_launch(void* const* d_in, const int* in_sizes, int n_in,
                              void* d_out, int out_size) {
    const float* x     = (const float*)d_in[0];
    const float* W_enc = (const float*)d_in[1];
    const float* b_enc = (const float*)d_in[2];
    const float* W1    = (const float*)d_in[3];
    const float* b1    = (const float*)d_in[4];
    const float* W2    = (const float*)d_in[5];
    const float* b2    = (const float*)d_in[6];
    const float* pos   = (const float*)d_in[7];

    float* out   = (float*)d_out;          // (B,P,D) first
    float* xcopy = out + OUT_T_ELEMS;      // then p = x passthrough

    k_all<<<PAIRS/2, 128>>>(x, xcopy, W_enc, b_enc, pos, W1, b1, W2, b2, out);
}

// round 15
// speedup vs baseline: 1.2478x; 1.2478x over previous
#include <cuda_runtime.h>
#include <cuda_bf16.h>

// Shapes (fixed): B=32, D=64, N=254, L=16, H=128, P=96
#define NB 32
#define ND 64
#define NN 254
#define NL 16
#define NH 128
#define NP 96
#define PAIRS (NB*ND)          // 2048
#define XPP (NN*NL)            // 4064 floats per (b,d) pair
#define OUT_T_ELEMS (NB*NP*ND) // 196608
#define NPRE 38                // producer blocks

// ---- shared precomputed tensors (tiny) ----
__device__ __align__(16) float g_constvec[NH];
__device__ __align__(16) float g_M[NN*NL];   // M[n,l] = pos[n,:] . W_enc[l,:]
__device__ __align__(16) float g_D2[NN];     // pos[n,:] . constvec
__device__ __align__(16) float g_G[NL*NL];   // G[l',l] = W_enc[l',:] . W_enc[l,:]
__device__ __align__(16) float g_u[NL];      // W_enc[l,:] . constvec
__device__ __align__(16) float g_wb[NL];     // W_enc[l,:] . b_enc
__device__ __align__(16) float g_s0pad[4];   // [0] = b_enc . constvec
__device__ int g_flag1;                       // constvec ready (monotone across replays)
__device__ int g_done;                        // precompute producers done (monotone)

__device__ __forceinline__ int ld_acq(const int* p) {
    int v;
    asm volatile("ld.acquire.gpu.global.b32 %0, [%1];" : "=r"(v) : "l"(p));
    return v;
}

// vectorized length-128 dot with 4 accumulators
__device__ __forceinline__ float dot128(const float4* __restrict__ a,
                                        const float4* __restrict__ b) {
    float s0=0.f, s1=0.f, s2=0.f, s3=0.f;
    #pragma unroll
    for (int i = 0; i < 32; i += 4) {
        float4 a0=a[i],   b0=b[i];
        float4 a1=a[i+1], b1=b[i+1];
        float4 a2=a[i+2], b2=b[i+2];
        float4 a3=a[i+3], b3=b[i+3];
        s0 += a0.x*b0.x + a0.y*b0.y + a0.z*b0.z + a0.w*b0.w;
        s1 += a1.x*b1.x + a1.y*b1.y + a1.z*b1.z + a1.w*b1.w;
        s2 += a2.x*b2.x + a2.y*b2.y + a2.z*b2.z + a2.w*b2.w;
        s3 += a3.x*b3.x + a3.y*b3.y + a3.z*b3.z + a3.w*b3.w;
    }
    return (s0+s1)+(s2+s3);
}

__global__ __launch_bounds__(128, 4)
void k_all(const float* __restrict__ x, float* __restrict__ x_copy,
           const float* __restrict__ W_enc, const float* __restrict__ b_enc,
           const float* __restrict__ pos,
           const float* __restrict__ W1, const float* __restrict__ b1,
           const float* __restrict__ W2, const float* __restrict__ b2,
           float* __restrict__ out_t) {
    __shared__ __align__(16) float  hdnT[NH*4];       // [h][pair-in-block]
    __shared__ __align__(16) float4 red7[4][4][24];   // [warp][pair][p-float4]

    const int tid  = threadIdx.x;
    const int pid  = blockIdx.x;
    const int lane = tid & 31;
    const int wrp  = tid >> 5;
    const int q    = lane & 3;         // l-quarter index
    const int r    = lane >> 2;        // row-within-8 index
    const float4* __restrict__ pos4 = (const float4*)pos;
    const float4* __restrict__ W4   = (const float4*)W_enc;

    // ---------- inline precompute (first NPRE blocks; wave-1 co-resident) ----------
    if (pid < NPRE) {
        if (pid == 0) {
            float a0=0.f, a1=0.f, a2=0.f, a3=0.f;
            #pragma unroll 2
            for (int n = 0; n < 252; n += 4) {
                a0 += __ldg(pos + (n+0)*NH + tid);
                a1 += __ldg(pos + (n+1)*NH + tid);
                a2 += __ldg(pos + (n+2)*NH + tid);
                a3 += __ldg(pos + (n+3)*NH + tid);
            }
            a0 += __ldg(pos + 252*NH + tid);
            a1 += __ldg(pos + 253*NH + tid);
            g_constvec[tid] = (float)NN * b_enc[tid] + ((a0+a1)+(a2+a3));
            __threadfence();
            __syncthreads();
            if (tid == 0) atomicAdd(&g_flag1, 1);
        } else if (pid <= 34) {
            int j = (pid-1)*128 + tid;
            if (j < NN*NL) {                         // M
                g_M[j] = dot128(pos4 + (j>>4)*32, W4 + (j&15)*32);
            } else if (j < NN*NL + NL*NL) {          // G
                int k = j - NN*NL;
                g_G[k] = dot128(W4 + (k>>4)*32, W4 + (k&15)*32);
            }
        } else {
            if (tid == 0) { while (ld_acq(&g_flag1) == 0) {} }
            __syncthreads();
            const float4* cv4 = (const float4*)g_constvec;
            int j = (pid-35)*128 + tid;
            if (j < NN) {                            // D2
                g_D2[j] = dot128(pos4 + j*32, cv4);
            } else if (j < NN + NL) {                // u
                g_u[j-NN] = dot128(W4 + (j-NN)*32, cv4);
            } else if (j < NN + 2*NL) {              // wb
                g_wb[j-NN-NL] = dot128(W4 + (j-NN-NL)*32, (const float4*)b_enc);
            } else if (j == NN + 2*NL) {             // s0
                g_s0pad[0] = dot128((const float4*)b_enc, cv4);
            }
        }
        __threadfence();
        __syncthreads();
        if (tid == 0) atomicAdd(&g_done, 1);
    }

    // ---------- warp-per-pair main path (identical to R10 champion) ----------
    const int pair = pid*4 + wrp;
    const float4* __restrict__ xp4 = (const float4*)(x + (size_t)pair * XPP);
    float4* __restrict__ xc4 = (float4*)(x_copy + (size_t)pair * XPP);

    // Pass 1: stream x (cached) + passthrough copy + xsum partials.
    float ls0=0.f, ls1=0.f, ls2=0.f, ls3=0.f;
    #pragma unroll 8
    for (int j = 0; j < 32; j++) {
        int i = j*32 + lane;
        if (i < XPP/4) {
            float4 f = xp4[i];
            __stcs(xc4 + i, f);
            ls0 += f.x; ls1 += f.y; ls2 += f.z; ls3 += f.w;
        }
    }
    #pragma unroll
    for (int m = 4; m <= 16; m <<= 1) {
        ls0 += __shfl_xor_sync(0xffffffffu, ls0, m);
        ls1 += __shfl_xor_sync(0xffffffffu, ls1, m);
        ls2 += __shfl_xor_sync(0xffffffffu, ls2, m);
        ls3 += __shfl_xor_sync(0xffffffffu, ls3, m);
    }

    // wait for precompute (first pairs only; nearly-free afterwards)
    while (ld_acq(&g_done) < NPRE) {}

    // materialize xsum[0..15] per lane
    float xs[16];
    #pragma unroll
    for (int a = 0; a < 4; a++) {
        xs[4*a+0] = __shfl_sync(0xffffffffu, ls0, a);
        xs[4*a+1] = __shfl_sync(0xffffffffu, ls1, a);
        xs[4*a+2] = __shfl_sync(0xffffffffu, ls2, a);
        xs[4*a+3] = __shfl_sync(0xffffffffu, ls3, a);
    }
    float4 xsq = make_float4(ls0, ls1, ls2, ls3);   // own quarter of xsum

    // v (own quarter) = u_q + sum_l' xsum[l'] * G[l'][quarter q]
    const float4* __restrict__ G4 = (const float4*)g_G;
    float4 vq = __ldg(&((const float4*)g_u)[q]);
    #pragma unroll
    for (int lp = 0; lp < 16; lp++) {
        float4 g = __ldg(&G4[lp*4 + q]);
        vq.x += xs[lp]*g.x; vq.y += xs[lp]*g.y; vq.z += xs[lp]*g.z; vq.w += xs[lp]*g.w;
    }
    // sS = s0 + xsum . wb   (redundant per lane)
    float sS = __ldg(&g_s0pad[0]);
    {
        const float4* __restrict__ wb4 = (const float4*)g_wb;
        #pragma unroll
        for (int a = 0; a < 4; a++) {
            float4 w = __ldg(&wb4[a]);
            sS += xs[4*a+0]*w.x + xs[4*a+1]*w.y + xs[4*a+2]*w.z + xs[4*a+3]*w.w;
        }
    }

    // Pass 2: fused score + pool (x re-read, L1-hot)
    const float4* __restrict__ M4 = (const float4*)g_M;
    float p0=0.f, p1=0.f, p2=0.f, p3=0.f, myabs=0.f;
    #pragma unroll 8
    for (int j = 0; j < 32; j++) {
        int i = j*32 + lane;
        int n = j*8 + r;
        float4 f = make_float4(0.f,0.f,0.f,0.f);
        float4 m = make_float4(0.f,0.f,0.f,0.f);
        float d2 = 0.f;
        if (n < NN) {
            f  = xp4[i];
            m  = __ldg(&M4[n*4 + q]);
            d2 = __ldg(g_D2 + n);
        }
        float part = f.x*vq.x + f.y*vq.y + f.z*vq.z + f.w*vq.w
                   + xsq.x*m.x + xsq.y*m.y + xsq.z*m.z + xsq.w*m.w;
        part += __shfl_xor_sync(0xffffffffu, part, 1);
        part += __shfl_xor_sync(0xffffffffu, part, 2);
        float a = part + sS + d2;
        if (n < NN) {
            p0 += f.x*a; p1 += f.y*a; p2 += f.z*a; p3 += f.w*a;
            if (q == 0) myabs += fabsf(a);
        }
    }
    #pragma unroll
    for (int m = 4; m <= 16; m <<= 1) {
        p0 += __shfl_xor_sync(0xffffffffu, p0, m);
        p1 += __shfl_xor_sync(0xffffffffu, p1, m);
        p2 += __shfl_xor_sync(0xffffffffu, p2, m);
        p3 += __shfl_xor_sync(0xffffffffu, p3, m);
        myabs += __shfl_xor_sync(0xffffffffu, myabs, m);
    }
    float inv = 1.0f / __shfl_sync(0xffffffffu, myabs, 0);

    // materialize pooled[0..15] (unnormalized)
    float po[16];
    #pragma unroll
    for (int a = 0; a < 4; a++) {
        po[4*a+0] = __shfl_sync(0xffffffffu, p0, a);
        po[4*a+1] = __shfl_sync(0xffffffffu, p1, a);
        po[4*a+2] = __shfl_sync(0xffffffffu, p2, a);
        po[4*a+3] = __shfl_sync(0xffffffffu, p3, a);
    }

    // FF hidden: lane owns h = lane + 32k, k=0..3; deposit transposed to smem
    #pragma unroll
    for (int k = 0; k < 4; k++) {
        int h = lane + 32*k;
        float a = 0.f;
        #pragma unroll
        for (int l = 0; l < NL; l++) a += po[l] * __ldg(W1 + l*NH + h);
        a = __ldg(b1 + h) + a * inv;
        hdnT[h*4 + wrp] = (a > 0.f ? a : 0.2f * a);
    }
    __syncthreads();                                   // hdnT ready (all 4 pairs)

    // W2 block phase: warp w covers hh in [32w, 32w+32); one W2 row load serves
    // all 4 pairs (hv = hdnT4[hh] holds the 4 pairs' hidden values at hh).
    const float4* __restrict__ W24 = (const float4*)W2;    // [h][24] float4
    const float4* __restrict__ hT4 = (const float4*)hdnT;  // [h] -> (p0,p1,p2,p3)
    float4 a0 = make_float4(0.f,0.f,0.f,0.f);
    float4 a1 = make_float4(0.f,0.f,0.f,0.f);
    float4 a2 = make_float4(0.f,0.f,0.f,0.f);
    float4 a3 = make_float4(0.f,0.f,0.f,0.f);
    #pragma unroll 4
    for (int t = 0; t < 32; t++) {
        int hh = wrp*32 + t;
        float4 hv = hT4[hh];            // LDS.128 broadcast
        if (lane < 24) {
            float4 w4 = __ldg(&W24[hh*24 + lane]);
            a0.x += hv.x*w4.x; a0.y += hv.x*w4.y; a0.z += hv.x*w4.z; a0.w += hv.x*w4.w;
            a1.x += hv.y*w4.x; a1.y += hv.y*w4.y; a1.z += hv.y*w4.z; a1.w += hv.y*w4.w;
            a2.x += hv.z*w4.x; a2.y += hv.z*w4.y; a2.z += hv.z*w4.z; a2.w += hv.z*w4.w;
            a3.x += hv.w*w4.x; a3.y += hv.w*w4.y; a3.z += hv.w*w4.z; a3.w += hv.w*w4.w;
        }
    }
    if (lane < 24) {
        red7[wrp][0][lane] = a0;
        red7[wrp][1][lane] = a1;
        red7[wrp][2][lane] = a2;
        red7[wrp][3][lane] = a3;
    }
    __syncthreads();                                   // partials ready

    // warp wrp finalizes its own pair's output
    if (lane < 24) {
        float4 t0 = red7[0][wrp][lane];
        float4 t1 = red7[1][wrp][lane];
        float4 t2 = red7[2][wrp][lane];
        float4 t3 = red7[3][wrp][lane];
        float4 bb = __ldg(&((const float4*)b2)[lane]);
        int b = pair >> 6, d = pair & 63;
        float* dst = out_t + b*(NP*ND) + d;
        int p = lane*4;
        dst[(p+0)*ND] = (t0.x + t1.x) + (t2.x + t3.x) + bb.x;
        dst[(p+1)*ND] = (t0.y + t1.y) + (t2.y + t3.y) + bb.y;
        dst[(p+2)*ND] = (t0.z + t1.z) + (t2.z + t3.z) + bb.z;
        dst[(p+3)*ND] = (t0.w + t1.w) + (t2.w + t3.w) + bb.w;
    }
}

extern "C" void kernel_launch(void* const* d_in, const int* in_sizes, int n_in,
                              void* d_out, int out_size) {
    const float* x     = (const float*)d_in[0];
    const float* W_enc = (const float*)d_in[1];
    const float* b_enc = (const float*)d_in[2];
    const float* W1    = (const float*)d_in[3];
    const float* b1    = (const float*)d_in[4];
    const float* W2    = (const float*)d_in[5];
    const float* b2    = (const float*)d_in[6];
    const float* pos   = (const float*)d_in[7];

    float* out   = (float*)d_out;          // (B,P,D) first
    float* xcopy = out + OUT_T_ELEMS;      // then p = x passthrough

    k_all<<<PAIRS/4, 128>>>(x, xcopy, W_enc, b_enc, pos, W1, b1, W2, b2, out);
}